// round 9
// baseline (speedup 1.0000x reference)
#include <cuda_runtime.h>
#include <math.h>
#include <stdint.h>

#define BB 64
#define SS 512
#define DD 1024
#define HH 1024
#define GG 4096   // 4*H
#define NBLK 128  // persistent blocks (1/SM via smem)

// Scratch (allocation-free rule: __device__ globals)
__device__ float g_xproj[(size_t)BB * SS * GG];  // [B*S, 4H], m = b*S + t (includes bih+bhh)
__device__ float g_h[2][BB * HH];                // ping-pong hidden state
__device__ float g_c[BB * HH];                   // cell state
__device__ unsigned int g_bar_count;             // grid barrier
__device__ volatile unsigned int g_bar_gen;

__device__ __forceinline__ float sigmoidf_(float x) {
    return 1.0f / (1.0f + expf(-x));
}

__device__ __forceinline__ void cp16(uint32_t s, const void* g) {
    asm volatile("cp.async.cg.shared.global [%0], [%1], 16;\n" :: "r"(s), "l"(g));
}
#define CP_COMMIT() asm volatile("cp.async.commit_group;\n" ::: "memory")
#define CP_WAIT(N)  asm volatile("cp.async.wait_group %0;\n" :: "n"(N) : "memory")

#define MMA_TF32(C, A, B0, B1)                                               \
    asm volatile(                                                            \
        "mma.sync.aligned.m16n8k8.row.col.f32.tf32.tf32.f32 "                \
        "{%0,%1,%2,%3}, {%4,%5,%6,%7}, {%8,%9}, {%0,%1,%2,%3};\n"            \
        : "+f"((C)[0]), "+f"((C)[1]), "+f"((C)[2]), "+f"((C)[3])             \
        : "r"((A)[0]), "r"((A)[1]), "r"((A)[2]), "r"((A)[3]),                \
          "r"(B0), "r"(B1))

// ---------------------------------------------------------------------------
__global__ void init_state(const float* __restrict__ h0, const float* __restrict__ c0) {
    int i = blockIdx.x * blockDim.x + threadIdx.x;
    if (i < BB * HH) {
        g_h[0][i] = h0[i];
        g_c[i]    = c0[i];
    }
}

// ---------------------------------------------------------------------------
// xproj (tf32 MMA): C[32768, 4096] = X @ Wih^T + (bih + bhh)
// Block tile 256(M) x 128(N), 512 threads (16 warps), warp tile 64x32.
// ---------------------------------------------------------------------------
#define XBM 256
#define XBN 128
#define XBK 32
#define XSTRIDE 36
#define XA_ELEMS (XBM * XSTRIDE)
#define XB_ELEMS (XBN * XSTRIDE)
#define XSMEM_BYTES ((2 * XA_ELEMS + 2 * XB_ELEMS) * 4)

__global__ __launch_bounds__(512) void xproj_mma(
    const float* __restrict__ X,
    const float* __restrict__ Wih,
    const float* __restrict__ bih,
    const float* __restrict__ bhh)
{
    extern __shared__ float xsm[];
    float* As = xsm;
    float* Bs = xsm + 2 * XA_ELEMS;

    const int m0 = blockIdx.y * XBM;
    const int n0 = blockIdx.x * XBN;
    const int tid = threadIdx.x;
    const int wid = tid >> 5;
    const int lane = tid & 31;
    const int gid = lane >> 2;
    const int tg  = lane & 3;
    const int wm = wid & 3;      // m 64-rows
    const int wn = wid >> 2;     // n 32-cols

    const uint32_t As_s = (uint32_t)__cvta_generic_to_shared(As);
    const uint32_t Bs_s = (uint32_t)__cvta_generic_to_shared(Bs);

    auto load_tiles = [&](int k0, int buf) {
#pragma unroll
        for (int i = 0; i < 4; i++) {             // A: 256x32 -> 2048 units
            int u = tid + i * 512;
            int r = u >> 3;
            int c4 = (u & 7) * 4;
            cp16(As_s + (uint32_t)(buf * XA_ELEMS + r * XSTRIDE + c4) * 4,
                 X + (size_t)(m0 + r) * DD + k0 + c4);
        }
#pragma unroll
        for (int i = 0; i < 2; i++) {             // B: 128x32 -> 1024 units
            int u = tid + i * 512;
            int r = u >> 3;
            int c4 = (u & 7) * 4;
            cp16(Bs_s + (uint32_t)(buf * XB_ELEMS + r * XSTRIDE + c4) * 4,
                 Wih + (size_t)(n0 + r) * DD + k0 + c4);
        }
    };

    float acc[4][4][4];
#pragma unroll
    for (int a = 0; a < 4; a++)
#pragma unroll
        for (int b = 0; b < 4; b++)
#pragma unroll
            for (int c = 0; c < 4; c++) acc[a][b][c] = 0.0f;

    load_tiles(0, 0);
    CP_COMMIT();

#pragma unroll 1
    for (int kc = 0; kc < DD / XBK; kc++) {
        int cur = kc & 1;
        if (kc + 1 < DD / XBK) {
            load_tiles((kc + 1) * XBK, cur ^ 1);
            CP_COMMIT();
            CP_WAIT(1);
        } else {
            CP_WAIT(0);
        }
        __syncthreads();

        const float* ab = As + cur * XA_ELEMS;
        const float* bb = Bs + cur * XB_ELEMS;

#pragma unroll
        for (int ks = 0; ks < 4; ks++) {
            int kb = ks * 8;
            uint32_t af[4][4];
#pragma unroll
            for (int mi = 0; mi < 4; mi++) {
                int row = wm * 64 + mi * 16 + gid;
                af[mi][0] = __float_as_uint(ab[row * XSTRIDE + kb + tg]);
                af[mi][1] = __float_as_uint(ab[(row + 8) * XSTRIDE + kb + tg]);
                af[mi][2] = __float_as_uint(ab[row * XSTRIDE + kb + tg + 4]);
                af[mi][3] = __float_as_uint(ab[(row + 8) * XSTRIDE + kb + tg + 4]);
            }
#pragma unroll
            for (int ni = 0; ni < 4; ni++) {
                int nrow = wn * 32 + ni * 8 + gid;
                uint32_t b0 = __float_as_uint(bb[nrow * XSTRIDE + kb + tg]);
                uint32_t b1 = __float_as_uint(bb[nrow * XSTRIDE + kb + tg + 4]);
#pragma unroll
                for (int mi = 0; mi < 4; mi++) MMA_TF32(acc[mi][ni], af[mi], b0, b1);
            }
        }
        __syncthreads();
    }

#pragma unroll
    for (int ni = 0; ni < 4; ni++) {
        int n = n0 + wn * 32 + ni * 8 + tg * 2;
        float bv0 = bih[n] + bhh[n];
        float bv1 = bih[n + 1] + bhh[n + 1];
#pragma unroll
        for (int mi = 0; mi < 4; mi++) {
            int m = m0 + wm * 64 + mi * 16 + gid;
            float2 v0 = make_float2(acc[mi][ni][0] + bv0, acc[mi][ni][1] + bv1);
            *(float2*)(g_xproj + (size_t)m * GG + n) = v0;
            float2 v1 = make_float2(acc[mi][ni][2] + bv0, acc[mi][ni][3] + bv1);
            *(float2*)(g_xproj + (size_t)(m + 8) * GG + n) = v1;
        }
    }
}

// ---------------------------------------------------------------------------
// Persistent LSTM. 128 blocks, 1/SM, 512 threads (16 warps).
// Block bx: j-cols [bx*8, bx*8+8), all 64 batches, 4 gates (32 Whh rows).
// Warp layout: mw = wid&1 (32-batch half), kh = wid>>1 (8 K-eighths of 128).
// Each warp: 32(batch) x 32(gatecols) x 128(K) -> 8 m16n8 C tiles.
// h streamed in 8 chunks of 128 cols; chunk c stages, for each K-eighth s,
// cols [s*128 + c*16, +16). Partial sums in 8 SMEM slabs (aliased onto the
// h staging buffers), reduced in the fused epilogue. One sync per chunk.
// ---------------------------------------------------------------------------
#define WS_STRIDE 1028                 // 1024+4 -> conflict-free (stride 4 mod 32)
#define WS_TOT (32 * WS_STRIDE)        // 32896 floats
#define NCH 8
#define HS_STRIDE 132
#define HS_ELEMS (64 * HS_STRIDE)      // 8448 floats per buffer
#define GSLAB (4 * 64 * 8)             // 2048 floats per K-slab
#define CSM_ELEMS 512
#define PSMEM_FLOATS (WS_TOT + 2 * HS_ELEMS + CSM_ELEMS)
#define PSMEM_BYTES (PSMEM_FLOATS * 4)  // 201,216 B  (gsm aliases hs)

__device__ __forceinline__ void grid_barrier(int tid) {
    __threadfence();
    __syncthreads();
    if (tid == 0) {
        unsigned int gen = g_bar_gen;
        if (atomicAdd(&g_bar_count, 1) == NBLK - 1) {
            g_bar_count = 0;
            __threadfence();
            g_bar_gen = gen + 1;
        } else {
            while (g_bar_gen == gen) { }
        }
    }
    __syncthreads();
}

__global__ __launch_bounds__(512, 1) void lstm_persist(
    const float* __restrict__ Whh,
    float* __restrict__ out)
{
    extern __shared__ float sm[];
    float* ws  = sm;                         // [32][WS_STRIDE] weights (persistent)
    float* hs  = ws + WS_TOT;                // [2][64][HS_STRIDE] h chunk staging
    float* gsm = hs;                         // [8][4][64][8] partials (ALIAS, epilogue only)
    float* csm = hs + 2 * HS_ELEMS;          // [512] cell slice (persistent)

    const int j0  = blockIdx.x * 8;
    const int tid = threadIdx.x;
    const int wid = tid >> 5;
    const int lane = tid & 31;
    const int gid = lane >> 2;
    const int tg  = lane & 3;
    const int mw = wid & 1;            // batch half (32 rows)
    const int kh = wid >> 1;           // K eighth (128 k)

    const uint32_t ws_s = (uint32_t)__cvta_generic_to_shared(ws);
    const uint32_t hs_s = (uint32_t)__cvta_generic_to_shared(hs);

    // ---- one-time: load Whh slice (32 rows x 1024) into SMEM ----
#pragma unroll 4
    for (int i = 0; i < 16; i++) {
        int u = tid + i * 512;               // 0..8191 16B-units
        int r = u >> 8;                      // row = g*8 + jj
        int c4 = (u & 255) * 4;
        int n = (r >> 3) * HH + j0 + (r & 7);
        cp16(ws_s + (uint32_t)(r * WS_STRIDE + c4) * 4, Whh + (size_t)n * HH + c4);
    }
    CP_COMMIT();

    // ---- precompute loader addresses (4 cp16 per chunk per thread) ----
    // unit u covers hs[row][c4..c4+3]; global col = seg*128 + c*16 + (c4&15)
    int ld_goff[4];      // row*HH + seg*128 + within  (add c*16 per chunk)
    uint32_t ld_soff[4]; // byte offset inside one hs buffer
#pragma unroll
    for (int i = 0; i < 4; i++) {
        int u = tid + i * 512;
        int row = u >> 5;
        int c4 = (u & 31) * 4;
        ld_goff[i] = row * HH + (c4 >> 4) * 128 + (c4 & 15);
        ld_soff[i] = (uint32_t)(row * HS_STRIDE + c4) * 4;
    }

    // ---- one-time: cell slice + epilogue indices (1 elem/thread) ----
    const int b_e  = tid >> 3;
    const int jj_e = tid & 7;
    const int nj_e = j0 + jj_e;
    const size_t xb_e = (size_t)b_e * SS * GG + nj_e;
    const size_t ob_e = (size_t)b_e * SS * HH + nj_e;
    csm[tid] = g_c[b_e * HH + nj_e];
    CP_WAIT(0);
    __syncthreads();

    // weight row pointers for this warp's 4 gate n8-tiles, at its K-eighth
    const float* wptr[4];
#pragma unroll
    for (int g = 0; g < 4; g++)
        wptr[g] = ws + (size_t)(g * 8 + gid) * WS_STRIDE + kh * 128 + tg;

    const int arow0 = mw * 32 + gid;   // A rows: arow0, +8, +16, +24
    const int kloc = kh * 16;          // warp's col base within a staged chunk

#pragma unroll 1
    for (int t = 0; t < SS; t++) {
        const float* __restrict__ h_in = g_h[t & 1];
        float* __restrict__ h_out = g_h[(t + 1) & 1];

        // issue chunk 0
        {
            uint32_t base = hs_s;  // buf 0
#pragma unroll
            for (int i = 0; i < 4; i++)
                cp16(base + ld_soff[i], h_in + ld_goff[i]);
        }
        CP_COMMIT();

        // prefetch xproj gate tile for (block, t)
        float xp[4];
#pragma unroll
        for (int g = 0; g < 4; g++)
            xp[g] = __ldg(&g_xproj[xb_e + (size_t)t * GG + g * HH]);

        float acc0[4][4], acc1[4][4];
#pragma unroll
        for (int g = 0; g < 4; g++)
#pragma unroll
            for (int r = 0; r < 4; r++) { acc0[g][r] = 0.f; acc1[g][r] = 0.f; }

#pragma unroll 1
        for (int c = 0; c < NCH; c++) {
            CP_WAIT(0);
            __syncthreads();
            if (c + 1 < NCH) {
                uint32_t base = hs_s + (uint32_t)(((c + 1) & 1) * HS_ELEMS) * 4;
                int goff = (c + 1) * 16;
#pragma unroll
                for (int i = 0; i < 4; i++)
                    cp16(base + ld_soff[i], h_in + ld_goff[i] + goff);
                CP_COMMIT();
            }

            const float* hb = hs + (c & 1) * HS_ELEMS;
            const int kw = c * 16;     // k offset within warp's K-eighth

#pragma unroll
            for (int ks = 0; ks < 2; ks++) {
                int kb = kloc + ks * 8;
                uint32_t a0[4], a1[4];
                a0[0] = __float_as_uint(hb[(arow0)      * HS_STRIDE + kb + tg]);
                a0[1] = __float_as_uint(hb[(arow0 + 8)  * HS_STRIDE + kb + tg]);
                a0[2] = __float_as_uint(hb[(arow0)      * HS_STRIDE + kb + tg + 4]);
                a0[3] = __float_as_uint(hb[(arow0 + 8)  * HS_STRIDE + kb + tg + 4]);
                a1[0] = __float_as_uint(hb[(arow0 + 16) * HS_STRIDE + kb + tg]);
                a1[1] = __float_as_uint(hb[(arow0 + 24) * HS_STRIDE + kb + tg]);
                a1[2] = __float_as_uint(hb[(arow0 + 16) * HS_STRIDE + kb + tg + 4]);
                a1[3] = __float_as_uint(hb[(arow0 + 24) * HS_STRIDE + kb + tg + 4]);

#pragma unroll
                for (int g = 0; g < 4; g++) {
                    uint32_t b0 = __float_as_uint(wptr[g][kw + ks * 8]);
                    uint32_t b1 = __float_as_uint(wptr[g][kw + ks * 8 + 4]);
                    MMA_TF32(acc0[g], a0, b0, b1);
                    MMA_TF32(acc1[g], a1, b0, b1);
                }
            }
        }

        // all compute done before gsm (aliased over hs) is written
        __syncthreads();

        // stash partials: gsm[kh][g][batch][jj]
        {
            float* gs = gsm + kh * GSLAB;
            int r0 = mw * 32 + gid;
#pragma unroll
            for (int g = 0; g < 4; g++) {
                gs[(g * 64 + r0)      * 8 + tg * 2 + 0] = acc0[g][0];
                gs[(g * 64 + r0)      * 8 + tg * 2 + 1] = acc0[g][1];
                gs[(g * 64 + r0 + 8)  * 8 + tg * 2 + 0] = acc0[g][2];
                gs[(g * 64 + r0 + 8)  * 8 + tg * 2 + 1] = acc0[g][3];
                gs[(g * 64 + r0 + 16) * 8 + tg * 2 + 0] = acc1[g][0];
                gs[(g * 64 + r0 + 16) * 8 + tg * 2 + 1] = acc1[g][1];
                gs[(g * 64 + r0 + 24) * 8 + tg * 2 + 0] = acc1[g][2];
                gs[(g * 64 + r0 + 24) * 8 + tg * 2 + 1] = acc1[g][3];
            }
        }
        __syncthreads();

        // fused cell update (1 element/thread; reduce 8 K-slabs)
        {
            int base = b_e * 8 + jj_e;
            float gv4[4];
#pragma unroll
            for (int g = 0; g < 4; g++) {
                float s = xp[g];
#pragma unroll
                for (int sl = 0; sl < 8; sl++)
                    s += gsm[sl * GSLAB + (g * 64) * 8 + base];
                gv4[g] = s;
            }

            float iv = sigmoidf_(gv4[0]);
            float fv = sigmoidf_(gv4[1]);
            float gv = tanhf(gv4[2]);
            float ov = sigmoidf_(gv4[3]);

            float cc = fv * csm[tid] + iv * gv;
            csm[tid] = cc;
            float h = ov * tanhf(cc);
            h_out[b_e * HH + nj_e] = h;
            out[ob_e + (size_t)t * HH] = h;
        }

        grid_barrier(tid);
    }

    // write back cell state
    g_c[b_e * HH + nj_e] = csm[tid];
}

// ---------------------------------------------------------------------------
__global__ void write_final(float* __restrict__ tail) {
    int i = blockIdx.x * blockDim.x + threadIdx.x;
    if (i < BB * HH) {
        tail[i] = g_h[SS & 1][i];
        tail[BB * HH + i] = g_c[i];
    }
}

// ---------------------------------------------------------------------------
extern "C" void kernel_launch(void* const* d_in, const int* in_sizes, int n_in,
                              void* d_out, int out_size) {
    const float* X   = (const float*)d_in[0];  // [B,S,D]
    const float* h0  = (const float*)d_in[1];  // [1,B,H]
    const float* c0  = (const float*)d_in[2];  // [1,B,H]
    const float* Wih = (const float*)d_in[3];  // [4H,D]
    const float* Whh = (const float*)d_in[4];  // [4H,H]
    const float* bih = (const float*)d_in[5];  // [4H]
    const float* bhh = (const float*)d_in[6];  // [4H]
    float* out = (float*)d_out;                // outputs [B,S,H] | hn | cn

    cudaFuncSetAttribute(xproj_mma,
                         cudaFuncAttributeMaxDynamicSharedMemorySize, XSMEM_BYTES);
    cudaFuncSetAttribute(lstm_persist,
                         cudaFuncAttributeMaxDynamicSharedMemorySize, PSMEM_BYTES);

    init_state<<<(BB * HH + 255) / 256, 256>>>(h0, c0);

    dim3 gx(GG / XBN, (BB * SS) / XBM);
    xproj_mma<<<gx, 512, XSMEM_BYTES>>>(X, Wih, bih, bhh);

    lstm_persist<<<NBLK, 512, PSMEM_BYTES>>>(Whh, out);

    write_final<<<(BB * HH + 255) / 256, 256>>>(out + (size_t)BB * SS * HH);
}